// round 12
// baseline (speedup 1.0000x reference)
#include <cuda_runtime.h>
#include <cuda_bf16.h>

#define FULL 0xffffffffu

static __device__ __forceinline__ unsigned long long pk2(float lo, float hi) {
    unsigned long long r;
    asm("mov.b64 %0, {%1,%2};" : "=l"(r) : "f"(lo), "f"(hi));
    return r;
}
static __device__ __forceinline__ void upk2(unsigned long long v, float& lo, float& hi) {
    asm("mov.b64 {%0,%1}, %2;" : "=f"(lo), "=f"(hi) : "l"(v));
}
static __device__ __forceinline__ unsigned long long fma2(unsigned long long a,
                                                          unsigned long long b,
                                                          unsigned long long c) {
    unsigned long long d;
    asm("fma.rn.f32x2 %0,%1,%2,%3;" : "=l"(d) : "l"(a), "l"(b), "l"(c));
    return d;
}
static __device__ __forceinline__ unsigned long long add2(unsigned long long a,
                                                           unsigned long long b) {
    unsigned long long d;
    asm("add.rn.f32x2 %0,%1,%2;" : "=l"(d) : "l"(a), "l"(b));
    return d;
}
static __device__ __forceinline__ unsigned long long mul2(unsigned long long a,
                                                           unsigned long long b) {
    unsigned long long d;
    asm("mul.rn.f32x2 %0,%1,%2;" : "=l"(d) : "l"(a), "l"(b));
    return d;
}

static constexpr int Bb = 256;
static constexpr int Tt = 2048;
static constexpr int Dd = 64;
static constexpr int NSEG = 8;
static constexpr int SEGT = Tt / NSEG;

__device__ float s12p[Bb][NSEG];
__device__ int   Lg[Bb];

// ============================================================================
// Pass 1a: valid length per batch.
// ============================================================================
__global__ __launch_bounds__(256) void len_kernel(const int* __restrict__ mask) {
    const int b = blockIdx.x, tid = threadIdx.x, w = tid >> 5, l = tid & 31;
    __shared__ int red[8];
    const int4* m4 = reinterpret_cast<const int4*>(mask + (size_t)b * Tt);
    int4 a = m4[tid], c = m4[256 + tid];
    int s = a.x + a.y + a.z + a.w + c.x + c.y + c.z + c.w;
#pragma unroll
    for (int o = 16; o > 0; o >>= 1) s += __shfl_xor_sync(FULL, s, o);
    if (l == 0) red[w] = s;
    __syncthreads();
    if (tid == 0) {
        int tot = 0;
#pragma unroll
        for (int j = 0; j < 8; j++) tot += red[j];
        Lg[b] = Tt - tot;
    }
}

// ============================================================================
// Pass 1b: emission + transition score partial for one (batch, segment).
// ============================================================================
__global__ __launch_bounds__(256) void score_kernel(
    const float* __restrict__ p,
    const int*   __restrict__ y,
    const float* __restrict__ trans)
{
    const int blk = blockIdx.x;
    const int b = blk >> 3, seg = blk & (NSEG - 1);
    const int tid = threadIdx.x, w = tid >> 5, l = tid & 31;
    const int t0 = seg * SEGT;

    __shared__ short lab[SEGT + 1];
    __shared__ float red[8];

    const int2* yB = reinterpret_cast<const int2*>(y + (size_t)b * Tt * Dd);
    for (int i = w; i <= SEGT; i += 8) {
        int t = t0 + i;
        if (t < Tt) {
            int2 yv = yB[t * 32 + l];
            unsigned bx = __ballot_sync(FULL, yv.x != 0);
            unsigned by = __ballot_sync(FULL, yv.y != 0);
            if (l == 0)
                lab[i] = bx ? (short)(2 * (__ffs(bx) - 1))
                            : (short)(2 * (__ffs(by) - 1) + 1);
        }
    }
    __syncthreads();

    const int L = Lg[b];
    const int t = t0 + tid;
    const int lt = lab[tid];
    float acc = 0.f;
    if (t < L)     acc += __ldg(&p[(size_t)b * Tt * Dd + (size_t)t * Dd + lt]);
    if (t + 1 < L) acc += __ldg(&trans[lt * Dd + lab[tid + 1]]);

#pragma unroll
    for (int o = 16; o > 0; o >>= 1) acc += __shfl_xor_sync(FULL, acc, o);
    if (l == 0) red[w] = acc;
    __syncthreads();
    if (tid == 0) {
        float tot = 0.f;
#pragma unroll
        for (int j = 0; j < 8; j++) tot += red[j];
        s12p[b][seg] = tot;
    }
}

// ============================================================================
// Pass 2: forward recurrence. One block = 2 warps = ONE batch.
// Warp w reduces over state rows [32w, 32w+32): 16 LDS.128 + 32 FFMA2 per
// step (64-cyc fma issue, half the solo-warp floor). Both warps run identical
// instruction streams; one __syncthreads per step for the partial exchange.
// Partials stored pre-duplicated and pre-scaled by ep2, so the post-barrier
// combine is LDS.128 + 2 add2. State array DOUBLE-BUFFERED (t&1) and
// partitioned so each warp reads only its own warp's stores.
// Linear domain with power-of-two renormalization; p staged in 8-step chunks.
// ============================================================================
static constexpr int CH  = 8;
static constexpr int NCH = Tt / CH;

__global__ __launch_bounds__(64) void crf_forward_kernel(
    const float* __restrict__ p,       // [B,T,D]
    const float* __restrict__ trans,   // [D,D]
    float*       __restrict__ out)     // [B]
{
    const int tid = threadIdx.x;
    const int w   = tid >> 5;          // 0,1
    const int l   = tid & 31;
    const int b   = blockIdx.x;

    // stateDup2[buf][i] = { {v[2i],v[2i]}, {v[2i+1],v[2i+1]} }
    // entries [0,16) written by warp0 lanes 0..15; [16,32) by warp1 lanes 16..31
    __shared__ __align__(16) ulonglong2 stateDup2[2][32];
    __shared__ __align__(16) ulonglong2 partDup[2][2][32];  // [warp][buf][lane]
    __shared__ float sp[2][CH][Dd];                          // staged p chunks

    const int L = Lg[b];

    // expT rows [32w, 32w+32), cols (2l, 2l+1): 32 packed u64 regs
    unsigned long long eT[32];
#pragma unroll
    for (int j = 0; j < 32; j++) {
        float2 tv = reinterpret_cast<const float2*>(trans)[(32 * w + j) * 32 + l];
        eT[j] = pk2(__expf(tv.x), __expf(tv.y));
    }

    const float4* p4 = reinterpret_cast<const float4*>(p + (size_t)b * Tt * Dd);

    // stage chunks 0,1 (2 float4/thread each); prefetch chunk 2
    float4 prf[2];
#pragma unroll
    for (int j = 0; j < 2; j++) {
        reinterpret_cast<float4*>(sp[0])[tid + 64 * j] = p4[tid + 64 * j];
        reinterpret_cast<float4*>(sp[1])[tid + 64 * j] = p4[128 + tid + 64 * j];
        prf[j] = p4[256 + tid + 64 * j];
    }
    __syncthreads();

    // ---- t = 0 init: state for step 0 lives in buffer 0 ----
    float2 p0 = *reinterpret_cast<const float2*>(&sp[0][0][2 * l]);
    float vx = __expf(p0.x);
    float vy = __expf(p0.y);
    int ktot = 0;
    if ((l >> 4) == w) {
        ulonglong2 sv;
        sv.x = pk2(vx, vx);
        sv.y = pk2(vy, vy);
        stateDup2[0][l] = sv;
    }
    // renorm exponent from v[0] (lane 0 has it; identical in both warps)
    float v0 = __shfl_sync(FULL, vx, 0);
    int kx = (int)((__float_as_uint(v0) >> 23) & 255) - 127;

    for (int t = 1; t < L; t++) {
        const int ch = t >> 3, tb = t & 7, cb = ch & 1;
        const int sb = t & 1;        // state write buffer this step
        const int rb = sb ^ 1;       // state read buffer (prev step)

        if (tb == 0) {  // chunk boundary: commit chunk ch+1, prefetch ch+2
            reinterpret_cast<float4*>(sp[cb ^ 1])[tid]      = prf[0];
            reinterpret_cast<float4*>(sp[cb ^ 1])[tid + 64] = prf[1];
            const int nc = min(ch + 2, NCH - 1);
            prf[0] = p4[nc * 128 + tid];
            prf[1] = p4[nc * 128 + tid + 64];
        }

        // emission + renorm (off critical path)
        float2 pt = *reinterpret_cast<const float2*>(&sp[cb][tb][2 * l]);
        const int k = kx;
        ktot += k;
        float sc = __uint_as_float((unsigned)(127 - k) << 23);  // 2^{-k}
        unsigned long long ep2 = pk2(__expf(pt.x) * sc, __expf(pt.y) * sc);

        // partial matvec over my 32 rows: 16 LDS.128 + 32 FFMA2
        const ulonglong2* myState = stateDup2[rb] + 16 * w;
        unsigned long long a0 = 0, a1 = 0, a2 = 0, a3 = 0;
#pragma unroll
        for (int j = 0; j < 16; j += 2) {
            ulonglong2 q0 = myState[j + 0];
            ulonglong2 q1 = myState[j + 1];
            a0 = fma2(q0.x, eT[2 * j + 0], a0);
            a1 = fma2(q0.y, eT[2 * j + 1], a1);
            a2 = fma2(q1.x, eT[2 * j + 2], a2);
            a3 = fma2(q1.y, eT[2 * j + 3], a3);
        }
        unsigned long long S = add2(add2(a0, a1), add2(a2, a3));
        unsigned long long P = mul2(S, ep2);  // pre-scale by ep2

        // store duplicated partial
        float Px, Py;
        upk2(P, Px, Py);
        ulonglong2 Pd;
        Pd.x = pk2(Px, Px);
        Pd.y = pk2(Py, Py);
        partDup[w][sb][l] = Pd;

        __syncthreads();

        // combine with partner's partial (already duplicated + scaled)
        ulonglong2 Qd = partDup[w ^ 1][sb][l];
        ulonglong2 Vd;
        Vd.x = add2(Pd.x, Qd.x);
        Vd.y = add2(Pd.y, Qd.y);
        if ((l >> 4) == w) stateDup2[sb][l] = Vd;  // commit my region

        float dup;
        upk2(Vd.x, vx, dup);
        upk2(Vd.y, vy, dup);

        // next step's renorm exponent (off-path, warp-local shfl — both warps
        // compute bit-identical vx so kx agrees across warps)
        float v0n = __shfl_sync(FULL, vx, 0);
        kx = (int)((__float_as_uint(v0n) >> 23) & 255) - 127;
    }

    // ---- finalize (warp 0): logZ = log(sum v) + ktot*ln2 - s12 ----
    if (w == 0) {
        float sumv = vx + vy;
#pragma unroll
        for (int o = 16; o > 0; o >>= 1) sumv += __shfl_xor_sync(FULL, sumv, o);
        if (l == 0) {
            float s12 = 0.f;
#pragma unroll
            for (int j = 0; j < NSEG; j++) s12 += s12p[b][j];
            out[b] = logf(sumv) + (float)ktot * 0.6931471805599453f - s12;
        }
    }
}

extern "C" void kernel_launch(void* const* d_in, const int* in_sizes, int n_in,
                              void* d_out, int out_size) {
    const float* p     = (const float*)d_in[0];
    const int*   y     = (const int*)d_in[1];
    const int*   mask  = (const int*)d_in[2];
    const float* trans = (const float*)d_in[3];
    float* out = (float*)d_out;
    len_kernel<<<Bb, 256>>>(mask);
    score_kernel<<<Bb * NSEG, 256>>>(p, y, trans);
    crf_forward_kernel<<<Bb, 64>>>(p, trans, out);
}